// round 2
// baseline (speedup 1.0000x reference)
#include <cuda_runtime.h>
#include <cuda_bf16.h>
#include <math.h>

// Problem constants
#define BB 256
#define TT 512
#define DD 512
#define HH 256
#define KK 3
#define MM (BB * TT)   // 131072 rows

// Scratch: emission scores em[B*T, K]
__device__ float g_em[MM * KK];
__device__ float g_partial[8];

// ---------------------------------------------------------------------------
// Kernel 1: fused  em = gelu(x @ W1 + b1) @ W2 + b2
// Block: 256 threads, computes 64 rows x full H=256 cols of h in registers,
// then reduces to em (64 x 3) in the epilogue (h never hits memory).
// Tiling: BM=64, BK=16, per-thread microtile 8x8.
//   warp w (=tid/32) owns rows w*8..w*8+7 ; lane tx owns cols {j*32+tx}.
// ---------------------------------------------------------------------------
__global__ __launch_bounds__(256, 2)
void fused_mlp_kernel(const float* __restrict__ x,
                      const float* __restrict__ W1,
                      const float* __restrict__ b1,
                      const float* __restrict__ W2,
                      const float* __restrict__ b2)
{
    __shared__ float s_x[64 * 16];     // x tile   [64 rows][16 k]
    __shared__ float s_w[16 * 256];    // W1 tile  [16 k][256 h]
    __shared__ float s_w2[256 * 3];    // W2       [256 h][3 k]
    __shared__ float s_b1[256];

    const int tid = threadIdx.x;
    const int ty  = tid >> 5;          // warp id 0..7
    const int tx  = tid & 31;          // lane
    const int row_base = blockIdx.x * 64;

    // Preload W2 and b1 (small, once per block)
    #pragma unroll
    for (int i = 0; i < 3; ++i) s_w2[tid + i * 256] = W2[tid + i * 256];
    s_b1[tid] = b1[tid];

    float acc[8][8];
    #pragma unroll
    for (int i = 0; i < 8; ++i)
        #pragma unroll
        for (int j = 0; j < 8; ++j) acc[i][j] = 0.0f;

    // K loop over D=512 in chunks of 16
    for (int k0 = 0; k0 < DD; k0 += 16) {
        __syncthreads();
        // load x tile: 64x16 = 256 float4, one per thread
        {
            const int r = tid >> 2;          // 0..63
            const int q = (tid & 3) << 2;    // 0,4,8,12
            const float4 v = *reinterpret_cast<const float4*>(
                &x[(size_t)(row_base + r) * DD + k0 + q]);
            *reinterpret_cast<float4*>(&s_x[r * 16 + q]) = v;
        }
        // load W1 tile: 16x256 = 1024 float4, 4 per thread
        #pragma unroll
        for (int p = 0; p < 4; ++p) {
            const int l = tid * 4 + p * 1024;        // float index 0..4095
            const float4 v = *reinterpret_cast<const float4*>(
                &W1[(size_t)k0 * HH + l]);
            *reinterpret_cast<float4*>(&s_w[l]) = v;
        }
        __syncthreads();

        #pragma unroll
        for (int kk = 0; kk < 16; ++kk) {
            float xr[8], wr[8];
            #pragma unroll
            for (int i = 0; i < 8; ++i) xr[i] = s_x[(ty * 8 + i) * 16 + kk];
            #pragma unroll
            for (int j = 0; j < 8; ++j) wr[j] = s_w[kk * 256 + j * 32 + tx];
            #pragma unroll
            for (int i = 0; i < 8; ++i)
                #pragma unroll
                for (int j = 0; j < 8; ++j)
                    acc[i][j] = fmaf(xr[i], wr[j], acc[i][j]);
        }
    }

    // Epilogue: bias + exact gelu + GEMM2 partials, then warp reduction.
    float pem[8][3];
    #pragma unroll
    for (int i = 0; i < 8; ++i)
        #pragma unroll
        for (int c = 0; c < 3; ++c) pem[i][c] = 0.0f;

    #pragma unroll
    for (int j = 0; j < 8; ++j) {
        const int col = j * 32 + tx;
        const float w20 = s_w2[col * 3 + 0];
        const float w21 = s_w2[col * 3 + 1];
        const float w22 = s_w2[col * 3 + 2];
        const float bb1 = s_b1[col];
        #pragma unroll
        for (int i = 0; i < 8; ++i) {
            const float v = acc[i][j] + bb1;
            const float h = 0.5f * v * (1.0f + erff(v * 0.7071067811865476f));
            pem[i][0] = fmaf(h, w20, pem[i][0]);
            pem[i][1] = fmaf(h, w21, pem[i][1]);
            pem[i][2] = fmaf(h, w22, pem[i][2]);
        }
    }

    // butterfly all-reduce across the 32 lanes (sum over H columns)
    #pragma unroll
    for (int off = 16; off > 0; off >>= 1) {
        #pragma unroll
        for (int i = 0; i < 8; ++i)
            #pragma unroll
            for (int c = 0; c < 3; ++c)
                pem[i][c] += __shfl_xor_sync(0xffffffffu, pem[i][c], off);
    }

    if (tx == 0) {
        const float bb0 = b2[0], bb1_ = b2[1], bb2_ = b2[2];
        #pragma unroll
        for (int i = 0; i < 8; ++i) {
            const size_t r = (size_t)(row_base + ty * 8 + i) * 3;
            g_em[r + 0] = pem[i][0] + bb0;
            g_em[r + 1] = pem[i][1] + bb1_;
            g_em[r + 2] = pem[i][2] + bb2_;
        }
    }
}

// ---------------------------------------------------------------------------
// Kernel 2: CRF log-likelihood. One thread per batch, 8 blocks x 32 threads.
// ---------------------------------------------------------------------------
__device__ __forceinline__ float sel3(float a, float b, float c, int i) {
    return (i == 0) ? a : ((i == 1) ? b : c);
}
__device__ __forceinline__ float lse3(float x, float y, float z) {
    const float m = fmaxf(fmaxf(x, y), z);
    return m + __logf(__expf(x - m) + __expf(y - m) + __expf(z - m));
}

__global__ void crf_kernel(const int* __restrict__ tags,
                           const int* __restrict__ lengths,
                           const float* __restrict__ trans,
                           const float* __restrict__ start,
                           const float* __restrict__ end)
{
    const int b = blockIdx.x * 32 + threadIdx.x;   // 0..255

    const float t00 = trans[0], t01 = trans[1], t02 = trans[2];
    const float t10 = trans[3], t11 = trans[4], t12 = trans[5];
    const float t20 = trans[6], t21 = trans[7], t22 = trans[8];
    const float st0 = start[0], st1 = start[1], st2 = start[2];
    const float en0 = end[0],   en1 = end[1],   en2 = end[2];

    const int len = max(lengths[b], 1);
    const float* eb = &g_em[(size_t)b * TT * 3];
    const int*   tg = &tags[(size_t)b * TT];

    float e0 = eb[0], e1 = eb[1], e2 = eb[2];
    int tp = tg[0];
    float num = sel3(st0, st1, st2, tp) + sel3(e0, e1, e2, tp);
    float a0 = st0 + e0, a1 = st1 + e1, a2 = st2 + e2;

    for (int t = 1; t < len; ++t) {
        e0 = eb[t * 3 + 0]; e1 = eb[t * 3 + 1]; e2 = eb[t * 3 + 2];
        const float n0 = lse3(a0 + t00, a1 + t10, a2 + t20) + e0;
        const float n1 = lse3(a0 + t01, a1 + t11, a2 + t21) + e1;
        const float n2 = lse3(a0 + t02, a1 + t12, a2 + t22) + e2;
        a0 = n0; a1 = n1; a2 = n2;

        const int tc = tg[t];
        const float trv =
            (tp == 0) ? sel3(t00, t01, t02, tc)
          : (tp == 1) ? sel3(t10, t11, t12, tc)
                      : sel3(t20, t21, t22, tc);
        num += trv + sel3(e0, e1, e2, tc);
        tp = tc;
    }
    num += sel3(en0, en1, en2, tp);
    const float denom = lse3(a0 + en0, a1 + en1, a2 + en2);

    float llh = num - denom;
    #pragma unroll
    for (int off = 16; off > 0; off >>= 1)
        llh += __shfl_xor_sync(0xffffffffu, llh, off);
    if (threadIdx.x == 0) g_partial[blockIdx.x] = llh;
}

__global__ void final_kernel(float* out) {
    float s = 0.0f;
    #pragma unroll
    for (int i = 0; i < 8; ++i) s += g_partial[i];
    out[0] = -s / (float)BB;
}

// ---------------------------------------------------------------------------
extern "C" void kernel_launch(void* const* d_in, const int* in_sizes, int n_in,
                              void* d_out, int out_size)
{
    const float* x       = (const float*)d_in[0];
    const int*   tags    = (const int*)  d_in[1];
    const int*   lengths = (const int*)  d_in[2];
    const float* W1      = (const float*)d_in[3];
    const float* b1      = (const float*)d_in[4];
    const float* W2      = (const float*)d_in[5];
    const float* b2      = (const float*)d_in[6];
    const float* trans   = (const float*)d_in[7];
    const float* start   = (const float*)d_in[8];
    const float* end     = (const float*)d_in[9];

    fused_mlp_kernel<<<MM / 64, 256>>>(x, W1, b1, W2, b2);
    crf_kernel<<<8, 32>>>(tags, lengths, trans, start, end);
    final_kernel<<<1, 1>>>((float*)d_out);
}

// round 3
// speedup vs baseline: 2.3005x; 2.3005x over previous
#include <cuda_runtime.h>
#include <cuda_bf16.h>
#include <math.h>

// Problem constants
#define BB 256
#define TT 512
#define DD 512
#define HH 256
#define KK 3
#define MM (BB * TT)   // 131072 rows

// Scratch
__device__ float g_em[TT * KK * BB];     // layout [t][k][b]  (coalesced for CRF)
__device__ int   g_tagsT[TT * BB];       // layout [t][b]
__device__ float g_partial[8];

// ---------------------------------------------------------------------------
// helpers
// ---------------------------------------------------------------------------
__device__ __forceinline__ unsigned f2tf(float f) {
    unsigned u;
    asm("cvt.rna.tf32.f32 %0, %1;" : "=r"(u) : "f"(f));
    return u;
}

__device__ __forceinline__ void mma_tf32(float (&d)[4],
                                         const unsigned (&a)[4],
                                         const unsigned (&b)[2]) {
    asm volatile(
        "mma.sync.aligned.m16n8k8.row.col.f32.tf32.tf32.f32 "
        "{%0,%1,%2,%3}, {%4,%5,%6,%7}, {%8,%9}, {%0,%1,%2,%3};\n"
        : "+f"(d[0]), "+f"(d[1]), "+f"(d[2]), "+f"(d[3])
        : "r"(a[0]), "r"(a[1]), "r"(a[2]), "r"(a[3]),
          "r"(b[0]), "r"(b[1]));
}

#define CP_ASYNC16(dst, src) \
    asm volatile("cp.async.cg.shared.global [%0], [%1], 16;\n" :: "r"(dst), "l"(src))
#define CP_COMMIT() asm volatile("cp.async.commit_group;\n")
#define CP_WAIT(n)  asm volatile("cp.async.wait_group %0;\n" :: "n"(n))

// ---------------------------------------------------------------------------
// Kernel 1: fused  em = gelu(x @ W1 + b1) @ W2 + b2   via tf32 tensor cores
// Block: 256 thr (8 warps). BM=64 rows, BN=256 (full H), BK=16.
// Warp w owns cols [w*32, w*32+32): 4x4 grid of m16n8k8 tiles.
// Epilogue fuses gelu + W2 contraction; h never touches memory.
// em written transposed [t][k][b] for the CRF kernel.
// ---------------------------------------------------------------------------
__global__ __launch_bounds__(256, 2)
void fused_mlp_tc(const float* __restrict__ x,
                  const float* __restrict__ W1,
                  const float* __restrict__ b1,
                  const float* __restrict__ W2,
                  const float* __restrict__ b2)
{
    __shared__ float s_x[2][64][20];     // x tile, padded (20) -> conflict-free frags
    __shared__ float s_w[2][16][264];    // W1 tile, padded (264)
    __shared__ float s_w2[256][3];
    __shared__ float s_b1[256];
    __shared__ float em_s[64][3];

    const int tid  = threadIdx.x;
    const int wid  = tid >> 5;
    const int lane = tid & 31;
    const int g    = lane >> 2;   // group id (row within 8)
    const int c    = lane & 3;    // thread-in-group (k / col pair)
    const int row_base = blockIdx.x * 64;
    const int cw   = wid * 32;    // warp's column base in H

    s_b1[tid]    = b1[tid];
    s_w2[tid][0] = W2[tid * 3 + 0];
    s_w2[tid][1] = W2[tid * 3 + 1];
    s_w2[tid][2] = W2[tid * 3 + 2];
    if (tid < 192) ((float*)em_s)[tid] = 0.0f;

    float acc[4][4][4];
    #pragma unroll
    for (int mt = 0; mt < 4; ++mt)
        #pragma unroll
        for (int nt = 0; nt < 4; ++nt)
            #pragma unroll
            for (int e = 0; e < 4; ++e) acc[mt][nt][e] = 0.0f;

    // ---- async tile loaders ----
    const int xr = tid >> 2;            // 0..63
    const int xq = (tid & 3) << 2;      // 0,4,8,12
    auto issue_stage = [&](int s, int k0) {
        unsigned dx = (unsigned)__cvta_generic_to_shared(&s_x[s][xr][xq]);
        CP_ASYNC16(dx, &x[(size_t)(row_base + xr) * DD + k0 + xq]);
        #pragma unroll
        for (int p = 0; p < 4; ++p) {
            const int chunk = tid + p * 256;      // 0..1023
            const int kr = chunk >> 6;            // 0..15
            const int c4 = (chunk & 63) << 2;     // 0..252
            unsigned dw = (unsigned)__cvta_generic_to_shared(&s_w[s][kr][c4]);
            CP_ASYNC16(dw, &W1[(size_t)(k0 + kr) * HH + c4]);
        }
        CP_COMMIT();
    };

    issue_stage(0, 0);

    const int NITER = DD / 16;  // 32
    for (int it = 0; it < NITER; ++it) {
        const int cur = it & 1;
        if (it + 1 < NITER) { issue_stage(cur ^ 1, (it + 1) * 16); CP_WAIT(1); }
        else                { CP_WAIT(0); }
        __syncthreads();

        #pragma unroll
        for (int ks = 0; ks < 2; ++ks) {
            const int kk = ks * 8;
            unsigned bf[4][2];
            #pragma unroll
            for (int nt = 0; nt < 4; ++nt) {
                const int n = cw + nt * 8 + g;
                bf[nt][0] = f2tf(s_w[cur][kk + c][n]);
                bf[nt][1] = f2tf(s_w[cur][kk + c + 4][n]);
            }
            #pragma unroll
            for (int mt = 0; mt < 4; ++mt) {
                const int r0 = mt * 16 + g;
                unsigned af[4];
                af[0] = f2tf(s_x[cur][r0][kk + c]);
                af[1] = f2tf(s_x[cur][r0 + 8][kk + c]);
                af[2] = f2tf(s_x[cur][r0][kk + c + 4]);
                af[3] = f2tf(s_x[cur][r0 + 8][kk + c + 4]);
                #pragma unroll
                for (int nt = 0; nt < 4; ++nt)
                    mma_tf32(acc[mt][nt], af, bf[nt]);
            }
        }
        __syncthreads();   // stage fully consumed before re-issue
    }

    // ---- epilogue: bias + exact gelu + W2 contraction ----
    float pem[8][3];   // 8 row slots: (mt, upper/lower) -> rows mt*16+g, mt*16+g+8
    #pragma unroll
    for (int i = 0; i < 8; ++i)
        #pragma unroll
        for (int k = 0; k < 3; ++k) pem[i][k] = 0.0f;

    #pragma unroll
    for (int mt = 0; mt < 4; ++mt)
        #pragma unroll
        for (int nt = 0; nt < 4; ++nt)
            #pragma unroll
            for (int e = 0; e < 4; ++e) {
                const int col = cw + nt * 8 + 2 * c + (e & 1);
                const int slot = mt * 2 + (e >> 1);
                const float v = acc[mt][nt][e] + s_b1[col];
                const float h = 0.5f * v * (1.0f + erff(v * 0.7071067811865476f));
                pem[slot][0] = fmaf(h, s_w2[col][0], pem[slot][0]);
                pem[slot][1] = fmaf(h, s_w2[col][1], pem[slot][1]);
                pem[slot][2] = fmaf(h, s_w2[col][2], pem[slot][2]);
            }

    // reduce across the 4 lanes that share a row (same g)
    #pragma unroll
    for (int d = 1; d < 4; d <<= 1)
        #pragma unroll
        for (int i = 0; i < 8; ++i)
            #pragma unroll
            for (int k = 0; k < 3; ++k)
                pem[i][k] += __shfl_xor_sync(0xffffffffu, pem[i][k], d);

    if (c == 0) {
        #pragma unroll
        for (int i = 0; i < 8; ++i) {
            const int row = (i >> 1) * 16 + g + (i & 1) * 8;
            atomicAdd(&em_s[row][0], pem[i][0]);
            atomicAdd(&em_s[row][1], pem[i][1]);
            atomicAdd(&em_s[row][2], pem[i][2]);
        }
    }
    __syncthreads();

    if (tid < 192) {
        const int r = tid / 3, k = tid % 3;
        const int m = row_base + r;
        const int b = m >> 9;          // m / 512
        const int t = m & 511;
        g_em[((size_t)t * 3 + k) * BB + b] = em_s[r][k] + b2[k];
    }
}

// ---------------------------------------------------------------------------
// tags transpose: [b][t] -> [t][b]
// ---------------------------------------------------------------------------
__global__ void transpose_tags_kernel(const int* __restrict__ tags) {
    __shared__ int tile[32][33];
    const int t0 = blockIdx.x * 32;
    const int b0 = blockIdx.y * 32;
    tile[threadIdx.y][threadIdx.x] = tags[(size_t)(b0 + threadIdx.y) * TT + t0 + threadIdx.x];
    __syncthreads();
    g_tagsT[(size_t)(t0 + threadIdx.y) * BB + b0 + threadIdx.x] =
        tile[threadIdx.x][threadIdx.y];
}

// ---------------------------------------------------------------------------
// Kernel 2: CRF. One thread per batch; coalesced [t][k][b] reads,
// 8-step register chunking to amortize memory latency.
// ---------------------------------------------------------------------------
__device__ __forceinline__ float sel3(float a, float b, float c, int i) {
    return (i == 0) ? a : ((i == 1) ? b : c);
}
__device__ __forceinline__ float lse3(float x, float y, float z) {
    const float m = fmaxf(fmaxf(x, y), z);
    return m + __logf(__expf(x - m) + __expf(y - m) + __expf(z - m));
}

__global__ void crf_kernel(const int* __restrict__ lengths,
                           const float* __restrict__ trans,
                           const float* __restrict__ start,
                           const float* __restrict__ end)
{
    const int b = blockIdx.x * 32 + threadIdx.x;   // 0..255

    const float t00 = trans[0], t01 = trans[1], t02 = trans[2];
    const float t10 = trans[3], t11 = trans[4], t12 = trans[5];
    const float t20 = trans[6], t21 = trans[7], t22 = trans[8];
    const float st0 = start[0], st1 = start[1], st2 = start[2];
    const float en0 = end[0],   en1 = end[1],   en2 = end[2];

    const int len = max(lengths[b], 1);

    float e0 = g_em[0 * BB + b];
    float e1 = g_em[1 * BB + b];
    float e2 = g_em[2 * BB + b];
    int tp = g_tagsT[b];
    float num = sel3(st0, st1, st2, tp) + sel3(e0, e1, e2, tp);
    float a0 = st0 + e0, a1 = st1 + e1, a2 = st2 + e2;

    const int CH = 8;
    for (int t0 = 1; t0 < TT; t0 += CH) {
        if (t0 >= len) break;
        float ec[CH][3];
        int   tc[CH];
        #pragma unroll
        for (int j = 0; j < CH; ++j) {
            const int t = t0 + j;
            if (t < TT) {
                ec[j][0] = g_em[((size_t)t * 3 + 0) * BB + b];
                ec[j][1] = g_em[((size_t)t * 3 + 1) * BB + b];
                ec[j][2] = g_em[((size_t)t * 3 + 2) * BB + b];
                tc[j]    = g_tagsT[(size_t)t * BB + b];
            }
        }
        #pragma unroll
        for (int j = 0; j < CH; ++j) {
            const int t = t0 + j;
            if (t >= len) break;
            e0 = ec[j][0]; e1 = ec[j][1]; e2 = ec[j][2];
            const float n0 = lse3(a0 + t00, a1 + t10, a2 + t20) + e0;
            const float n1 = lse3(a0 + t01, a1 + t11, a2 + t21) + e1;
            const float n2 = lse3(a0 + t02, a1 + t12, a2 + t22) + e2;
            a0 = n0; a1 = n1; a2 = n2;

            const int tcur = tc[j];
            const float trv =
                (tp == 0) ? sel3(t00, t01, t02, tcur)
              : (tp == 1) ? sel3(t10, t11, t12, tcur)
                          : sel3(t20, t21, t22, tcur);
            num += trv + sel3(e0, e1, e2, tcur);
            tp = tcur;
        }
    }
    num += sel3(en0, en1, en2, tp);
    const float denom = lse3(a0 + en0, a1 + en1, a2 + en2);

    float llh = num - denom;
    #pragma unroll
    for (int off = 16; off > 0; off >>= 1)
        llh += __shfl_xor_sync(0xffffffffu, llh, off);
    if (threadIdx.x == 0) g_partial[blockIdx.x] = llh;
}

__global__ void final_kernel(float* out) {
    float s = 0.0f;
    #pragma unroll
    for (int i = 0; i < 8; ++i) s += g_partial[i];
    out[0] = -s / (float)BB;
}

// ---------------------------------------------------------------------------
extern "C" void kernel_launch(void* const* d_in, const int* in_sizes, int n_in,
                              void* d_out, int out_size)
{
    const float* x       = (const float*)d_in[0];
    const int*   tags    = (const int*)  d_in[1];
    const int*   lengths = (const int*)  d_in[2];
    const float* W1      = (const float*)d_in[3];
    const float* b1      = (const float*)d_in[4];
    const float* W2      = (const float*)d_in[5];
    const float* b2      = (const float*)d_in[6];
    const float* trans   = (const float*)d_in[7];
    const float* start   = (const float*)d_in[8];
    const float* end     = (const float*)d_in[9];

    fused_mlp_tc<<<MM / 64, 256>>>(x, W1, b1, W2, b2);
    transpose_tags_kernel<<<dim3(TT / 32, BB / 32), dim3(32, 32)>>>(tags);
    crf_kernel<<<8, 32>>>(lengths, trans, start, end);
    final_kernel<<<1, 1>>>((float*)d_out);
}